// round 1
// baseline (speedup 1.0000x reference)
#include <cuda_runtime.h>
#include <cstdint>

#define BB 8
#define CC_ 64
#define HH 128
#define WW 128

// Scratch (allowed: __device__ globals, no allocation)
__device__ float g_xT[BB*HH*WW*CC_];        // NHWC copy of x
__device__ float g_off[BB*HH*WW*18];        // offsets, [b][y][x][18]

// ---------- packed f32x2 helpers (Blackwell) ----------
__device__ __forceinline__ unsigned long long pk2(float lo, float hi){
    unsigned long long r;
    asm("mov.b64 %0, {%1, %2};" : "=l"(r) : "f"(lo), "f"(hi));
    return r;
}
__device__ __forceinline__ void unpk2(unsigned long long v, float& lo, float& hi){
    asm("mov.b64 {%0, %1}, %2;" : "=f"(lo), "=f"(hi) : "l"(v));
}
__device__ __forceinline__ unsigned long long fma2(unsigned long long a, unsigned long long b, unsigned long long c){
    unsigned long long d;
    asm("fma.rn.f32x2 %0, %1, %2, %3;" : "=l"(d) : "l"(a), "l"(b), "l"(c));
    return d;
}
__device__ __forceinline__ unsigned long long add2(unsigned long long a, unsigned long long b){
    unsigned long long d;
    asm("add.rn.f32x2 %0, %1, %2;" : "=l"(d) : "l"(a), "l"(b));
    return d;
}

// ---------------------------------------------------------------
// Kernel 1: NCHW -> NHWC transpose of x. One block per (y, b).
// ---------------------------------------------------------------
__global__ __launch_bounds__(256) void k_transpose(const float* __restrict__ x)
{
    __shared__ float sm[CC_][WW + 1];
    int y = blockIdx.x, b = blockIdx.y;
    const float* src = x + ((size_t)b * CC_) * (HH * WW) + (size_t)y * WW;
    for (int i = threadIdx.x; i < CC_ * WW; i += 256) {
        int c = i >> 7, xx = i & 127;
        sm[c][xx] = src[(size_t)c * (HH * WW) + xx];
    }
    __syncthreads();
    float* dst = g_xT + (size_t)(b * HH + y) * WW * CC_;
    for (int i = threadIdx.x; i < CC_ * WW; i += 256) {
        int xx = i >> 6, c = i & 63;
        dst[(size_t)xx * CC_ + c] = sm[c][xx];
    }
}

// ---------------------------------------------------------------
// Kernel 2: 3x3 conv 64->18 + bias + PReLU -> g_off [b][y][x][18]
// Block: 256 threads = 16x16 pixel tile of one image.
// f32x2 accumulators over output-channel pairs (9 pairs).
// ---------------------------------------------------------------
__global__ __launch_bounds__(256) void k_offset(const float* __restrict__ x,
                                                const float* __restrict__ ow,
                                                const float* __restrict__ ob,
                                                const float* __restrict__ pa)
{
    __shared__ float tile[8][18 * 18];   // 8-channel chunk, 18x18 halo tile
    __shared__ float2 wch[648];          // [c(8)][k(9)][opair(9)]

    int tx = threadIdx.x & 15, ty = threadIdx.x >> 4;
    int x0 = blockIdx.x * 16, y0 = blockIdx.y * 16, b = blockIdx.z;

    unsigned long long acc[9];
#pragma unroll
    for (int op = 0; op < 9; op++) acc[op] = pk2(ob[2 * op], ob[2 * op + 1]);

    for (int ch = 0; ch < 8; ch++) {
        int c0 = ch * 8;
        __syncthreads();
        // stage weight chunk
        for (int i = threadIdx.x; i < 648; i += 256) {
            int c = i / 81, r = i - c * 81;
            int k = r / 9, op = r - k * 9;
            int cg = c0 + c;
            wch[i] = make_float2(__ldg(&ow[(2 * op) * 576 + cg * 9 + k]),
                                 __ldg(&ow[(2 * op + 1) * 576 + cg * 9 + k]));
        }
        // stage input tile (zero-padded halo)
        for (int c = 0; c < 8; c++) {
            const float* xp = x + (size_t)(b * CC_ + c0 + c) * (HH * WW);
            for (int j = threadIdx.x; j < 324; j += 256) {
                int r = j / 18, col = j - r * 18;
                int gy = y0 - 1 + r, gx = x0 - 1 + col;
                float v = 0.f;
                if ((unsigned)gy < (unsigned)HH && (unsigned)gx < (unsigned)WW)
                    v = __ldg(&xp[gy * WW + gx]);
                tile[c][j] = v;
            }
        }
        __syncthreads();
#pragma unroll
        for (int c = 0; c < 8; c++) {
#pragma unroll
            for (int k = 0; k < 9; k++) {
                int ky = k / 3, kx = k - ky * 3;
                float v = tile[c][(ty + ky) * 18 + (tx + kx)];
                unsigned long long vv = pk2(v, v);
                const unsigned long long* wp =
                    reinterpret_cast<const unsigned long long*>(&wch[(c * 9 + k) * 9]);
#pragma unroll
                for (int op = 0; op < 9; op++)
                    acc[op] = fma2(vv, wp[op], acc[op]);
            }
        }
    }

    float a = __ldg(&pa[0]);
    int xx = x0 + tx, yy = y0 + ty;
    float2* dst = reinterpret_cast<float2*>(g_off + (size_t)((b * HH + yy) * WW + xx) * 18);
#pragma unroll
    for (int op = 0; op < 9; op++) {
        float lo, hi;
        unpk2(acc[op], lo, hi);
        lo = lo > 0.f ? lo : a * lo;
        hi = hi > 0.f ? hi : a * hi;
        dst[op] = make_float2(lo, hi);
    }
}

// ---------------------------------------------------------------
// Kernel 3: deformable grouped conv.
// Block 512 threads = 32 pixels of one row. Warp = 2 pixels x 16
// channel-quad lanes. Lanes q<9 precompute bilinear data for k=q,
// broadcast via SHFL. Corner gathers are float4 from NHWC (fully
// coalesced: 4 lines / LDG.128). Conv accum in f32x2 pairs; pair
// reduction over the two channel-halves via SHFL.XOR(1).
// ---------------------------------------------------------------
__global__ __launch_bounds__(512) void k_deform(const float* __restrict__ dw,
                                                const float* __restrict__ db,
                                                float* __restrict__ out)
{
    __shared__ float2 s_wq[2304];      // [cc(4)][k(9)][oi(4)][q(16)]
    __shared__ float s_out[64 * 33];   // padded pitch: conflict-free STS
    __shared__ float s_bias[64];

    int tid = threadIdx.x;
    if (tid < 64) s_bias[tid] = __ldg(&db[tid]);

    // stage grouped-conv weights, layout chosen for conflict-free LDS.64
    for (int i = tid; i < 2304; i += 512) {
        int q = i & 15, t = i >> 4;
        int oi = t & 3; t >>= 2;
        int k = t % 9, cc = t / 9;
        int g = q >> 1, cig = (q & 1) * 4 + cc;
        int o0 = g * 8 + 2 * oi;
        s_wq[i] = make_float2(__ldg(&dw[o0 * 72 + cig * 9 + k]),
                              __ldg(&dw[(o0 + 1) * 72 + cig * 9 + k]));
    }

    int lane = tid & 31, warp = tid >> 5;
    int q = lane & 15, ph = lane >> 4;
    int p = warp * 2 + ph;                 // pixel index within block (0..31)
    int b = blockIdx.z, y = blockIdx.y, x = blockIdx.x * 32 + p;

    // per-k bilinear setup (lanes q<9 of each pixel-half)
    float r_w00 = 0.f, r_w01 = 0.f, r_w10 = 0.f, r_w11 = 0.f, r_y0 = 0.f, r_x0 = 0.f;
    if (q < 9) {
        float2 d = __ldg(reinterpret_cast<const float2*>(
            g_off + (size_t)((b * HH + y) * WW + x) * 18 + 2 * q));
        float py  = (float)y + (float)(q / 3 - 1) + d.x;
        float pxx = (float)x + (float)(q % 3 - 1) + d.y;
        float y0f = floorf(py), x0f = floorf(pxx);
        float fy = py - y0f, fx = pxx - x0f;
        float vy0 = (y0f >= 0.f && y0f <= 127.f) ? 1.f : 0.f;
        float vy1 = (y0f >= -1.f && y0f <= 126.f) ? 1.f : 0.f;
        float vx0 = (x0f >= 0.f && x0f <= 127.f) ? 1.f : 0.f;
        float vx1 = (x0f >= -1.f && x0f <= 126.f) ? 1.f : 0.f;
        r_w00 = (1.f - fy) * (1.f - fx) * vy0 * vx0;
        r_w01 = (1.f - fy) * fx * vy0 * vx1;
        r_w10 = fy * (1.f - fx) * vy1 * vx0;
        r_w11 = fy * fx * vy1 * vx1;
        r_y0 = y0f; r_x0 = x0f;
    }
    __syncthreads();

    const float4* xb = reinterpret_cast<const float4*>(g_xT) + (size_t)b * HH * WW * 16 + q;

    unsigned long long acc[4] = {0ull, 0ull, 0ull, 0ull};  // 8 group outputs as 4 f32x2

#pragma unroll
    for (int k = 0; k < 9; k++) {
        int src = ph * 16 + k;
        float w00 = __shfl_sync(0xffffffffu, r_w00, src);
        float w01 = __shfl_sync(0xffffffffu, r_w01, src);
        float w10 = __shfl_sync(0xffffffffu, r_w10, src);
        float w11 = __shfl_sync(0xffffffffu, r_w11, src);
        int y0 = (int)__shfl_sync(0xffffffffu, r_y0, src);
        int x0 = (int)__shfl_sync(0xffffffffu, r_x0, src);
        int yc0 = min(max(y0, 0), HH - 1), yc1 = min(max(y0 + 1, 0), HH - 1);
        int xc0 = min(max(x0, 0), WW - 1), xc1 = min(max(x0 + 1, 0), WW - 1);

        float4 c00 = __ldg(&xb[(yc0 * WW + xc0) * 16]);
        float4 c01 = __ldg(&xb[(yc0 * WW + xc1) * 16]);
        float4 c10 = __ldg(&xb[(yc1 * WW + xc0) * 16]);
        float4 c11 = __ldg(&xb[(yc1 * WW + xc1) * 16]);

        float s[4];
        s[0] = w00 * c00.x + w01 * c01.x + w10 * c10.x + w11 * c11.x;
        s[1] = w00 * c00.y + w01 * c01.y + w10 * c10.y + w11 * c11.y;
        s[2] = w00 * c00.z + w01 * c01.z + w10 * c10.z + w11 * c11.z;
        s[3] = w00 * c00.w + w01 * c01.w + w10 * c10.w + w11 * c11.w;

#pragma unroll
        for (int cc = 0; cc < 4; cc++) {
            unsigned long long vv = pk2(s[cc], s[cc]);
            const unsigned long long* wp =
                reinterpret_cast<const unsigned long long*>(s_wq) + ((cc * 9 + k) * 4) * 16 + q;
#pragma unroll
            for (int oi = 0; oi < 4; oi++)
                acc[oi] = fma2(vv, wp[oi * 16], acc[oi]);
        }
    }

    // reduce the two channel-halves of each group (lane pair q, q^1)
#pragma unroll
    for (int oi = 0; oi < 4; oi++) {
        float lo, hi;
        unpk2(acc[oi], lo, hi);
        float lo2 = __shfl_xor_sync(0xffffffffu, lo, 1);
        float hi2 = __shfl_xor_sync(0xffffffffu, hi, 1);
        acc[oi] = add2(acc[oi], pk2(lo2, hi2));
    }

    {
        int g = q >> 1;
        int ob = g * 8 + (q & 1) * 4;  // even lane writes o 0..3, odd writes 4..7
        int oi0 = (q & 1) * 2;
        float v0, v1, v2, v3;
        unpk2(acc[oi0], v0, v1);
        unpk2(acc[oi0 + 1], v2, v3);
        s_out[(ob + 0) * 33 + p] = v0;
        s_out[(ob + 1) * 33 + p] = v1;
        s_out[(ob + 2) * 33 + p] = v2;
        s_out[(ob + 3) * 33 + p] = v3;
    }
    __syncthreads();

    // coalesced NCHW writeback (+bias)
    int xbase = blockIdx.x * 32;
    for (int i = tid; i < 64 * 32; i += 512) {
        int o = i >> 5, pp = i & 31;
        out[((size_t)(b * CC_ + o) * HH + y) * WW + xbase + pp] = s_out[o * 33 + pp] + s_bias[o];
    }
}

extern "C" void kernel_launch(void* const* d_in, const int* in_sizes, int n_in,
                              void* d_out, int out_size)
{
    const float* x  = (const float*)d_in[0];
    const float* ow = (const float*)d_in[1];
    const float* ob = (const float*)d_in[2];
    const float* pa = (const float*)d_in[3];
    const float* dw = (const float*)d_in[4];
    const float* db = (const float*)d_in[5];
    float* out = (float*)d_out;

    k_transpose<<<dim3(HH, BB), 256>>>(x);
    k_offset<<<dim3(WW / 16, HH / 16, BB), 256>>>(x, ow, ob, pa);
    k_deform<<<dim3(WW / 32, HH, BB), 512>>>(dw, db, out);
}

// round 2
// speedup vs baseline: 1.0020x; 1.0020x over previous
#include <cuda_runtime.h>
#include <cstdint>

#define BB 8
#define CC_ 64
#define HH 128
#define WW 128

// Scratch (allowed: __device__ globals, no allocation)
__device__ float g_xT[BB*HH*WW*CC_];        // NHWC copy of x
__device__ float g_off[BB*HH*WW*18];        // offsets, [b][y][x][18]

// ---------- packed f32x2 helpers (Blackwell) ----------
__device__ __forceinline__ unsigned long long pk2(float lo, float hi){
    unsigned long long r;
    asm("mov.b64 %0, {%1, %2};" : "=l"(r) : "f"(lo), "f"(hi));
    return r;
}
__device__ __forceinline__ void unpk2(unsigned long long v, float& lo, float& hi){
    asm("mov.b64 {%0, %1}, %2;" : "=f"(lo), "=f"(hi) : "l"(v));
}
__device__ __forceinline__ unsigned long long fma2(unsigned long long a, unsigned long long b, unsigned long long c){
    unsigned long long d;
    asm("fma.rn.f32x2 %0, %1, %2, %3;" : "=l"(d) : "l"(a), "l"(b), "l"(c));
    return d;
}
__device__ __forceinline__ unsigned long long add2(unsigned long long a, unsigned long long b){
    unsigned long long d;
    asm("add.rn.f32x2 %0, %1, %2;" : "=l"(d) : "l"(a), "l"(b));
    return d;
}

// ---------------------------------------------------------------
// Kernel 1: NCHW -> NHWC transpose of x. One block per (y, b).
// ---------------------------------------------------------------
__global__ __launch_bounds__(256) void k_transpose(const float* __restrict__ x)
{
    __shared__ float sm[CC_][WW + 1];
    int y = blockIdx.x, b = blockIdx.y;
    const float* src = x + ((size_t)b * CC_) * (HH * WW) + (size_t)y * WW;
    for (int i = threadIdx.x; i < CC_ * WW; i += 256) {
        int c = i >> 7, xx = i & 127;
        sm[c][xx] = src[(size_t)c * (HH * WW) + xx];
    }
    __syncthreads();
    float* dst = g_xT + (size_t)(b * HH + y) * WW * CC_;
    for (int i = threadIdx.x; i < CC_ * WW; i += 256) {
        int xx = i >> 6, c = i & 63;
        dst[(size_t)xx * CC_ + c] = sm[c][xx];
    }
}

// ---------------------------------------------------------------
// Kernel 2: 3x3 conv 64->18 + bias + PReLU -> g_off [b][y][x][18]
// Block: 256 threads = 16x16 pixel tile of one image.
// f32x2 accumulators over output-channel pairs (9 pairs).
// ---------------------------------------------------------------
__global__ __launch_bounds__(256) void k_offset(const float* __restrict__ x,
                                                const float* __restrict__ ow,
                                                const float* __restrict__ ob,
                                                const float* __restrict__ pa)
{
    __shared__ float tile[8][18 * 18];   // 8-channel chunk, 18x18 halo tile
    __shared__ float2 wch[648];          // [c(8)][k(9)][opair(9)]

    int tx = threadIdx.x & 15, ty = threadIdx.x >> 4;
    int x0 = blockIdx.x * 16, y0 = blockIdx.y * 16, b = blockIdx.z;

    unsigned long long acc[9];
#pragma unroll
    for (int op = 0; op < 9; op++) acc[op] = pk2(ob[2 * op], ob[2 * op + 1]);

    for (int ch = 0; ch < 8; ch++) {
        int c0 = ch * 8;
        __syncthreads();
        // stage weight chunk
        for (int i = threadIdx.x; i < 648; i += 256) {
            int c = i / 81, r = i - c * 81;
            int k = r / 9, op = r - k * 9;
            int cg = c0 + c;
            wch[i] = make_float2(__ldg(&ow[(2 * op) * 576 + cg * 9 + k]),
                                 __ldg(&ow[(2 * op + 1) * 576 + cg * 9 + k]));
        }
        // stage input tile (zero-padded halo)
        for (int c = 0; c < 8; c++) {
            const float* xp = x + (size_t)(b * CC_ + c0 + c) * (HH * WW);
            for (int j = threadIdx.x; j < 324; j += 256) {
                int r = j / 18, col = j - r * 18;
                int gy = y0 - 1 + r, gx = x0 - 1 + col;
                float v = 0.f;
                if ((unsigned)gy < (unsigned)HH && (unsigned)gx < (unsigned)WW)
                    v = __ldg(&xp[gy * WW + gx]);
                tile[c][j] = v;
            }
        }
        __syncthreads();
#pragma unroll
        for (int c = 0; c < 8; c++) {
#pragma unroll
            for (int k = 0; k < 9; k++) {
                int ky = k / 3, kx = k - ky * 3;
                float v = tile[c][(ty + ky) * 18 + (tx + kx)];
                unsigned long long vv = pk2(v, v);
                const unsigned long long* wp =
                    reinterpret_cast<const unsigned long long*>(&wch[(c * 9 + k) * 9]);
#pragma unroll
                for (int op = 0; op < 9; op++)
                    acc[op] = fma2(vv, wp[op], acc[op]);
            }
        }
    }

    float a = __ldg(&pa[0]);
    int xx = x0 + tx, yy = y0 + ty;
    float2* dst = reinterpret_cast<float2*>(g_off + (size_t)((b * HH + yy) * WW + xx) * 18);
#pragma unroll
    for (int op = 0; op < 9; op++) {
        float lo, hi;
        unpk2(acc[op], lo, hi);
        lo = lo > 0.f ? lo : a * lo;
        hi = hi > 0.f ? hi : a * hi;
        dst[op] = make_float2(lo, hi);
    }
}

// ---------------------------------------------------------------
// Kernel 3: deformable grouped conv.
// Block 512 threads = 32 pixels of one row. Warp = 2 pixels x 16
// channel-quad lanes. Lanes q<9 precompute bilinear data for k=q,
// broadcast via SHFL. Corner gathers are float4 from NHWC (fully
// coalesced: 4 lines / LDG.128). Conv accum in f32x2 pairs; pair
// reduction over the two channel-halves via SHFL.XOR(1).
// ---------------------------------------------------------------
__global__ __launch_bounds__(512) void k_deform(const float* __restrict__ dw,
                                                const float* __restrict__ db,
                                                float* __restrict__ out)
{
    __shared__ float2 s_wq[2304];      // [cc(4)][k(9)][oi(4)][q(16)]
    __shared__ float s_out[64 * 33];   // padded pitch: conflict-free STS
    __shared__ float s_bias[64];

    int tid = threadIdx.x;
    if (tid < 64) s_bias[tid] = __ldg(&db[tid]);

    // stage grouped-conv weights, layout chosen for conflict-free LDS.64
    for (int i = tid; i < 2304; i += 512) {
        int q = i & 15, t = i >> 4;
        int oi = t & 3; t >>= 2;
        int k = t % 9, cc = t / 9;
        int g = q >> 1, cig = (q & 1) * 4 + cc;
        int o0 = g * 8 + 2 * oi;
        s_wq[i] = make_float2(__ldg(&dw[o0 * 72 + cig * 9 + k]),
                              __ldg(&dw[(o0 + 1) * 72 + cig * 9 + k]));
    }

    int lane = tid & 31, warp = tid >> 5;
    int q = lane & 15, ph = lane >> 4;
    int p = warp * 2 + ph;                 // pixel index within block (0..31)
    int b = blockIdx.z, y = blockIdx.y, x = blockIdx.x * 32 + p;

    // per-k bilinear setup (lanes q<9 of each pixel-half)
    float r_w00 = 0.f, r_w01 = 0.f, r_w10 = 0.f, r_w11 = 0.f, r_y0 = 0.f, r_x0 = 0.f;
    if (q < 9) {
        float2 d = __ldg(reinterpret_cast<const float2*>(
            g_off + (size_t)((b * HH + y) * WW + x) * 18 + 2 * q));
        float py  = (float)y + (float)(q / 3 - 1) + d.x;
        float pxx = (float)x + (float)(q % 3 - 1) + d.y;
        float y0f = floorf(py), x0f = floorf(pxx);
        float fy = py - y0f, fx = pxx - x0f;
        float vy0 = (y0f >= 0.f && y0f <= 127.f) ? 1.f : 0.f;
        float vy1 = (y0f >= -1.f && y0f <= 126.f) ? 1.f : 0.f;
        float vx0 = (x0f >= 0.f && x0f <= 127.f) ? 1.f : 0.f;
        float vx1 = (x0f >= -1.f && x0f <= 126.f) ? 1.f : 0.f;
        r_w00 = (1.f - fy) * (1.f - fx) * vy0 * vx0;
        r_w01 = (1.f - fy) * fx * vy0 * vx1;
        r_w10 = fy * (1.f - fx) * vy1 * vx0;
        r_w11 = fy * fx * vy1 * vx1;
        r_y0 = y0f; r_x0 = x0f;
    }
    __syncthreads();

    const float4* xb = reinterpret_cast<const float4*>(g_xT) + (size_t)b * HH * WW * 16 + q;

    unsigned long long acc[4] = {0ull, 0ull, 0ull, 0ull};  // 8 group outputs as 4 f32x2

#pragma unroll
    for (int k = 0; k < 9; k++) {
        int src = ph * 16 + k;
        float w00 = __shfl_sync(0xffffffffu, r_w00, src);
        float w01 = __shfl_sync(0xffffffffu, r_w01, src);
        float w10 = __shfl_sync(0xffffffffu, r_w10, src);
        float w11 = __shfl_sync(0xffffffffu, r_w11, src);
        int y0 = (int)__shfl_sync(0xffffffffu, r_y0, src);
        int x0 = (int)__shfl_sync(0xffffffffu, r_x0, src);
        int yc0 = min(max(y0, 0), HH - 1), yc1 = min(max(y0 + 1, 0), HH - 1);
        int xc0 = min(max(x0, 0), WW - 1), xc1 = min(max(x0 + 1, 0), WW - 1);

        float4 c00 = __ldg(&xb[(yc0 * WW + xc0) * 16]);
        float4 c01 = __ldg(&xb[(yc0 * WW + xc1) * 16]);
        float4 c10 = __ldg(&xb[(yc1 * WW + xc0) * 16]);
        float4 c11 = __ldg(&xb[(yc1 * WW + xc1) * 16]);

        float s[4];
        s[0] = w00 * c00.x + w01 * c01.x + w10 * c10.x + w11 * c11.x;
        s[1] = w00 * c00.y + w01 * c01.y + w10 * c10.y + w11 * c11.y;
        s[2] = w00 * c00.z + w01 * c01.z + w10 * c10.z + w11 * c11.z;
        s[3] = w00 * c00.w + w01 * c01.w + w10 * c10.w + w11 * c11.w;

#pragma unroll
        for (int cc = 0; cc < 4; cc++) {
            unsigned long long vv = pk2(s[cc], s[cc]);
            const unsigned long long* wp =
                reinterpret_cast<const unsigned long long*>(s_wq) + ((cc * 9 + k) * 4) * 16 + q;
#pragma unroll
            for (int oi = 0; oi < 4; oi++)
                acc[oi] = fma2(vv, wp[oi * 16], acc[oi]);
        }
    }

    // reduce the two channel-halves of each group (lane pair q, q^1)
#pragma unroll
    for (int oi = 0; oi < 4; oi++) {
        float lo, hi;
        unpk2(acc[oi], lo, hi);
        float lo2 = __shfl_xor_sync(0xffffffffu, lo, 1);
        float hi2 = __shfl_xor_sync(0xffffffffu, hi, 1);
        acc[oi] = add2(acc[oi], pk2(lo2, hi2));
    }

    {
        int g = q >> 1;
        int ob = g * 8 + (q & 1) * 4;  // even lane writes o 0..3, odd writes 4..7
        int oi0 = (q & 1) * 2;
        float v0, v1, v2, v3;
        unpk2(acc[oi0], v0, v1);
        unpk2(acc[oi0 + 1], v2, v3);
        s_out[(ob + 0) * 33 + p] = v0;
        s_out[(ob + 1) * 33 + p] = v1;
        s_out[(ob + 2) * 33 + p] = v2;
        s_out[(ob + 3) * 33 + p] = v3;
    }
    __syncthreads();

    // coalesced NCHW writeback (+bias)
    int xbase = blockIdx.x * 32;
    for (int i = tid; i < 64 * 32; i += 512) {
        int o = i >> 5, pp = i & 31;
        out[((size_t)(b * CC_ + o) * HH + y) * WW + xbase + pp] = s_out[o * 33 + pp] + s_bias[o];
    }
}

extern "C" void kernel_launch(void* const* d_in, const int* in_sizes, int n_in,
                              void* d_out, int out_size)
{
    const float* x  = (const float*)d_in[0];
    const float* ow = (const float*)d_in[1];
    const float* ob = (const float*)d_in[2];
    const float* pa = (const float*)d_in[3];
    const float* dw = (const float*)d_in[4];
    const float* db = (const float*)d_in[5];
    float* out = (float*)d_out;

    k_transpose<<<dim3(HH, BB), 256>>>(x);
    k_offset<<<dim3(WW / 16, HH / 16, BB), 256>>>(x, ow, ob, pa);
    k_deform<<<dim3(WW / 32, HH, BB), 512>>>(dw, db, out);
}

// round 3
// speedup vs baseline: 1.2672x; 1.2646x over previous
#include <cuda_runtime.h>
#include <cstdint>

#define BB 8
#define HH 128
#define WW 128

__device__ float g_xT[BB*HH*WW*64];   // NHWC copy of x (emitted by k_offset_fused)
__device__ float g_off[BB*HH*WW*18];  // offsets [b][y][x][18]

typedef unsigned long long ull;
static __device__ __forceinline__ ull pk2(float lo, float hi){
    ull r; asm("mov.b64 %0, {%1, %2};" : "=l"(r) : "f"(lo), "f"(hi)); return r;
}
static __device__ __forceinline__ void unpk2(ull v, float& lo, float& hi){
    asm("mov.b64 {%0, %1}, %2;" : "=f"(lo), "=f"(hi) : "l"(v));
}
static __device__ __forceinline__ ull fma2(ull a, ull b, ull c){
    ull d; asm("fma.rn.f32x2 %0, %1, %2, %3;" : "=l"(d) : "l"(a), "l"(b), "l"(c)); return d;
}

// ---------------------------------------------------------------
// Kernel 1: offset conv 64->18 (3x3) + bias + PReLU -> g_off,
// AND emits NHWC x -> g_xT from the staged smem tiles.
// 256 thr = 32x16 pixel tile, 2 px/thread. 8-channel chunks.
// ---------------------------------------------------------------
__global__ __launch_bounds__(256) void k_offset_fused(const float* __restrict__ x,
                                                      const float* __restrict__ ow,
                                                      const float* __restrict__ ob,
                                                      const float* __restrict__ pa)
{
    __shared__ float tile[8*18*34];               // [c][r(18)][col(34)]
    __shared__ __align__(8) float wchf[1296];     // pairs: [(c*9+k)*9+op][2]

    int tid = threadIdx.x;
    int ty = tid >> 4, txq = (tid & 15) * 2;
    int x0 = blockIdx.x*32, y0 = blockIdx.y*16, b = blockIdx.z;

    ull acc0[9], acc1[9];
#pragma unroll
    for (int op = 0; op < 9; ++op){
        ull b2 = pk2(__ldg(&ob[2*op]), __ldg(&ob[2*op+1]));
        acc0[op] = b2; acc1[op] = b2;
    }

    for (int ch = 0; ch < 8; ++ch){
        int c0 = ch*8;
        __syncthreads();
        // weights: coalesced gmem read, scattered STS
        for (int i = tid; i < 1296; i += 256){
            int oc = i / 72, r = i - oc*72;            // r = c*9+k
            float v = __ldg(&ow[oc*576 + c0*9 + r]);
            wchf[(r*9 + (oc>>1))*2 + (oc&1)] = v;
        }
        // input tile with zero halo
        for (int i = tid; i < 4896; i += 256){
            int c = i / 612, rr = i - c*612;
            int r = rr / 34, col = rr - r*34;
            int gy = y0 - 1 + r, gx = x0 - 1 + col;
            float v = 0.f;
            if ((unsigned)gy < 128u && (unsigned)gx < 128u)
                v = __ldg(&x[((size_t)(b*64 + c0 + c)*128 + gy)*128 + gx]);
            tile[i] = v;
        }
        __syncthreads();

        // NHWC emit (replaces transpose kernel)
#pragma unroll
        for (int e = 0; e < 2; ++e){
            int base = (ty+1)*34 + (txq+1+e);
            float4 lo4, hi4;
            lo4.x = tile[0*612+base]; lo4.y = tile[1*612+base];
            lo4.z = tile[2*612+base]; lo4.w = tile[3*612+base];
            hi4.x = tile[4*612+base]; hi4.y = tile[5*612+base];
            hi4.z = tile[6*612+base]; hi4.w = tile[7*612+base];
            float4* dst = reinterpret_cast<float4*>(
                g_xT + ((size_t)(b*128 + y0+ty)*128 + x0+txq+e)*64 + c0);
            dst[0] = lo4; dst[1] = hi4;
        }

        // conv accumulate: row-reuse, 2 px share each weight load
        for (int c = 0; c < 8; ++c){
#pragma unroll
            for (int ky = 0; ky < 3; ++ky){
                int rbase = c*612 + (ty+ky)*34 + txq;
                float2 va = *reinterpret_cast<const float2*>(&tile[rbase]);
                float2 vb = *reinterpret_cast<const float2*>(&tile[rbase+2]);
                float vals[4] = {va.x, va.y, vb.x, vb.y};
#pragma unroll
                for (int kx = 0; kx < 3; ++kx){
                    ull vv0 = pk2(vals[kx],   vals[kx]);
                    ull vv1 = pk2(vals[kx+1], vals[kx+1]);
                    const ull* wp = reinterpret_cast<const ull*>(
                        &wchf[((c*9 + ky*3 + kx)*9)*2]);
#pragma unroll
                    for (int op = 0; op < 9; ++op){
                        ull w = wp[op];
                        acc0[op] = fma2(vv0, w, acc0[op]);
                        acc1[op] = fma2(vv1, w, acc1[op]);
                    }
                }
            }
        }
    }

    float a = __ldg(&pa[0]);
#pragma unroll
    for (int e = 0; e < 2; ++e){
        float2* dst = reinterpret_cast<float2*>(
            g_off + ((size_t)(b*128 + y0+ty)*128 + x0+txq+e)*18);
#pragma unroll
        for (int op = 0; op < 9; ++op){
            float lo, hi;
            unpk2(e ? acc1[op] : acc0[op], lo, hi);
            lo = lo > 0.f ? lo : a*lo;
            hi = hi > 0.f ? hi : a*hi;
            dst[op] = make_float2(lo, hi);
        }
    }
}

// ---------------------------------------------------------------
// Kernel 2: deformable grouped conv, two-phase per k.
// Block 512 thr = 64 pixels of one row.
//  A) warp = 2 px x 16 quad-lanes: coalesced float4 corner gathers
//     from NHWC, bilinear combine, STS.128 -> s_buf[p][c] (pitch 68).
//  B) warp = (group, pixel-half), lane = pixel: broadcast LDS.128
//     weights, private accumulation of all 8 cig per lane.
// ---------------------------------------------------------------
__global__ __launch_bounds__(512) void k_deform(const float* __restrict__ dw,
                                                const float* __restrict__ db,
                                                float* __restrict__ out)
{
    __shared__ __align__(16) float s_w[4608];   // [k][g][cig][o(8)]
    __shared__ __align__(16) float s_buf[64*68];
    __shared__ float s_bias[64];

    int tid = threadIdx.x;
    int lane = tid & 31, wid = tid >> 5;
    int b = blockIdx.z, y = blockIdx.y, x0 = blockIdx.x*64;

    if (tid < 64) s_bias[tid] = __ldg(&db[tid]);
    for (int i = tid; i < 4608; i += 512){
        float v = __ldg(&dw[i]);
        int og = i / 72, r = i - og*72;
        int cig = r / 9, k = r - cig*9;
        s_w[((k*8 + (og>>3))*8 + cig)*8 + (og&7)] = v;
    }

    int q = lane & 15, ph = lane >> 4;          // phase-A identity
    int gB = wid >> 1, hB = wid & 1;            // phase-B identity
    int pB = hB*32 + lane;

    // bilinear setup: lanes q<9 own kernel tap k=q for their pixel
    float rw00[2], rw01[2], rw10[2], rw11[2], ry0[2], rx0[2];
#pragma unroll
    for (int j = 0; j < 2; ++j){
        rw00[j]=rw01[j]=rw10[j]=rw11[j]=ry0[j]=rx0[j]=0.f;
        if (q < 9){
            int xx = x0 + wid*4 + j*2 + ph;
            float2 d = __ldg(reinterpret_cast<const float2*>(
                g_off + ((size_t)(b*128 + y)*128 + xx)*18 + 2*q));
            float py  = (float)y  + (float)(q/3 - 1) + d.x;
            float pxx = (float)xx + (float)(q%3 - 1) + d.y;
            float y0f = floorf(py), x0f = floorf(pxx);
            float fy = py - y0f, fx = pxx - x0f;
            float vy0 = (y0f >=  0.f && y0f <= 127.f) ? 1.f : 0.f;
            float vy1 = (y0f >= -1.f && y0f <= 126.f) ? 1.f : 0.f;
            float vx0 = (x0f >=  0.f && x0f <= 127.f) ? 1.f : 0.f;
            float vx1 = (x0f >= -1.f && x0f <= 126.f) ? 1.f : 0.f;
            rw00[j] = (1.f-fy)*(1.f-fx)*vy0*vx0;
            rw01[j] = (1.f-fy)*fx*vy0*vx1;
            rw10[j] = fy*(1.f-fx)*vy1*vx0;
            rw11[j] = fy*fx*vy1*vx1;
            ry0[j] = y0f; rx0[j] = x0f;
        }
    }

    const float4* xb = reinterpret_cast<const float4*>(g_xT)
                     + (size_t)b*(128*128*16) + q;
    ull acc[4] = {0ull, 0ull, 0ull, 0ull};

#pragma unroll 1
    for (int k = 0; k < 9; ++k){
        // ---- phase A: gather + bilinear -> s_buf ----
#pragma unroll
        for (int j = 0; j < 2; ++j){
            int src = ph*16 + k;
            float w00 = __shfl_sync(0xffffffffu, rw00[j], src);
            float w01 = __shfl_sync(0xffffffffu, rw01[j], src);
            float w10 = __shfl_sync(0xffffffffu, rw10[j], src);
            float w11 = __shfl_sync(0xffffffffu, rw11[j], src);
            int y0i = (int)__shfl_sync(0xffffffffu, ry0[j], src);
            int x0i = (int)__shfl_sync(0xffffffffu, rx0[j], src);
            int yc0 = min(max(y0i,   0), 127), yc1 = min(max(y0i+1, 0), 127);
            int xc0 = min(max(x0i,   0), 127), xc1 = min(max(x0i+1, 0), 127);
            float4 c00 = __ldg(&xb[(yc0*128 + xc0)*16]);
            float4 c01 = __ldg(&xb[(yc0*128 + xc1)*16]);
            float4 c10 = __ldg(&xb[(yc1*128 + xc0)*16]);
            float4 c11 = __ldg(&xb[(yc1*128 + xc1)*16]);
            float4 s;
            s.x = w00*c00.x + w01*c01.x + w10*c10.x + w11*c11.x;
            s.y = w00*c00.y + w01*c01.y + w10*c10.y + w11*c11.y;
            s.z = w00*c00.z + w01*c01.z + w10*c10.z + w11*c11.z;
            s.w = w00*c00.w + w01*c01.w + w10*c10.w + w11*c11.w;
            int p = wid*4 + j*2 + ph;
            *reinterpret_cast<float4*>(&s_buf[p*68 + 4*q]) = s;
        }
        __syncthreads();
        // ---- phase B: lane = pixel, broadcast weights ----
        {
            const float4* sp = reinterpret_cast<const float4*>(&s_buf[pB*68 + gB*8]);
            float4 sa = sp[0], sb4 = sp[1];
            float sm[8] = {sa.x, sa.y, sa.z, sa.w, sb4.x, sb4.y, sb4.z, sb4.w};
            const float4* wk = reinterpret_cast<const float4*>(&s_w[((k*8 + gB)*8)*8]);
#pragma unroll
            for (int cig = 0; cig < 8; ++cig){
                ull vv = pk2(sm[cig], sm[cig]);
                float4 wa = wk[cig*2], wb = wk[cig*2+1];
                acc[0] = fma2(vv, pk2(wa.x, wa.y), acc[0]);
                acc[1] = fma2(vv, pk2(wa.z, wa.w), acc[1]);
                acc[2] = fma2(vv, pk2(wb.x, wb.y), acc[2]);
                acc[3] = fma2(vv, pk2(wb.z, wb.w), acc[3]);
            }
        }
        __syncthreads();
    }

    // stage outputs [o][p] (pitch 65) and coalesced NCHW writeback
#pragma unroll
    for (int op = 0; op < 4; ++op){
        float lo, hi;
        unpk2(acc[op], lo, hi);
        s_buf[(gB*8 + 2*op    )*65 + pB] = lo;
        s_buf[(gB*8 + 2*op + 1)*65 + pB] = hi;
    }
    __syncthreads();
    for (int i = tid; i < 4096; i += 512){
        int o = i >> 6, p = i & 63;
        out[((size_t)(b*64 + o)*128 + y)*128 + x0 + p] = s_buf[o*65 + p] + s_bias[o];
    }
}

extern "C" void kernel_launch(void* const* d_in, const int* in_sizes, int n_in,
                              void* d_out, int out_size)
{
    const float* x  = (const float*)d_in[0];
    const float* ow = (const float*)d_in[1];
    const float* ob = (const float*)d_in[2];
    const float* pa = (const float*)d_in[3];
    const float* dw = (const float*)d_in[4];
    const float* db = (const float*)d_in[5];
    float* out = (float*)d_out;

    k_offset_fused<<<dim3(4, 8, 8), 256>>>(x, ow, ob, pa);
    k_deform<<<dim3(2, 128, 8), 512>>>(dw, db, out);
}